// round 5
// baseline (speedup 1.0000x reference)
#include <cuda_runtime.h>
#include <cuda_fp16.h>
#include <cstdint>

#define NN   100000
#define EE   3200000
#define FH   256
#define FIN  512
#define FOUT 64
#define HOPS 10

// ---------------- scratch (device globals) ----------------------------------
__device__ __half g_x16 [(size_t)NN * FIN];
__device__ __half g_x016[(size_t)NN * FH];
__device__ __half g_h16 [(size_t)NN * FH];
__device__ __half g_t16 [(size_t)NN * FH];
__device__ __half g_W1t [(size_t)FIN * FH];
__device__ __half g_W3p [(size_t)FH * FH];
__device__ __half g_W2t [(size_t)FH * FOUT];
__device__ int    g_rowstart[NN + 1];
__device__ int    g_cnt[NN];
__device__ int2   g_epack[EE];

// ---------------- conversions ------------------------------------------------
__global__ void x2h_kernel(const float* __restrict__ x) {
    size_t i = (size_t)blockIdx.x * blockDim.x + threadIdx.x;
    if (i >= (size_t)NN * FIN / 8) return;
    float4 a = __ldg(((const float4*)x) + 2 * i);
    float4 b = __ldg(((const float4*)x) + 2 * i + 1);
    uint4 o;
    ((__half2*)&o)[0] = __floats2half2_rn(a.x, a.y);
    ((__half2*)&o)[1] = __floats2half2_rn(a.z, a.w);
    ((__half2*)&o)[2] = __floats2half2_rn(b.x, b.y);
    ((__half2*)&o)[3] = __floats2half2_rn(b.z, b.w);
    ((uint4*)g_x16)[i] = o;
}

__global__ void wt_kernel(const float* __restrict__ W, __half* __restrict__ Bt,
                          int K, int Nc, int addI) {
    int i = blockIdx.x * blockDim.x + threadIdx.x;
    if (i >= K * Nc) return;
    int n = i / K, k = i % K;
    float v = __ldg(&W[(size_t)k * Nc + n]);
    if (addI && k == n) v += 1.0f;
    Bt[i] = __float2half_rn(v);
}

// ---------------- CSR build --------------------------------------------------
__global__ void zero_cnt_kernel() {
    int i = blockIdx.x * blockDim.x + threadIdx.x;
    if (i < NN) g_cnt[i] = 0;
}

__global__ void hist_kernel(const int* __restrict__ erow) {
    int e = blockIdx.x * blockDim.x + threadIdx.x;
    if (e < EE) atomicAdd(&g_cnt[erow[e]], 1);
}

// exclusive scan; also seeds g_cnt with the offsets so scatter needs no 2nd zero
__global__ void scan_kernel() {
    __shared__ int wsum[32];
    __shared__ int carry_s;
    int t = threadIdx.x, lane = t & 31, w = t >> 5;
    if (t == 0) carry_s = 0;
    __syncthreads();
    for (int base = 0; base < NN; base += 1024) {
        int i = base + t;
        int v = (i < NN) ? g_cnt[i] : 0;
        int s = v;
        #pragma unroll
        for (int off = 1; off < 32; off <<= 1) {
            int u = __shfl_up_sync(0xffffffff, s, off);
            if (lane >= off) s += u;
        }
        if (lane == 31) wsum[w] = s;
        __syncthreads();
        if (w == 0) {
            int ws = wsum[lane];
            #pragma unroll
            for (int off = 1; off < 32; off <<= 1) {
                int u = __shfl_up_sync(0xffffffff, ws, off);
                if (lane >= off) ws += u;
            }
            wsum[lane] = ws;
        }
        __syncthreads();
        int wpre = (w == 0) ? 0 : wsum[w - 1];
        if (i < NN) {
            int rs = carry_s + wpre + s - v;
            g_rowstart[i] = rs;
            g_cnt[i] = rs;           // scatter cursor
        }
        __syncthreads();
        if (t == 1023) carry_s += wsum[31];
        __syncthreads();
    }
    if (threadIdx.x == 0) g_rowstart[NN] = carry_s;
}

__global__ void scatter_kernel(const int* __restrict__ erow,
                               const int* __restrict__ ecol,
                               const float* __restrict__ eval) {
    int e = blockIdx.x * blockDim.x + threadIdx.x;
    if (e < EE) {
        int p = atomicAdd(&g_cnt[erow[e]], 1);
        g_epack[p] = make_int2(ecol[e], __float_as_int(eval[e]));
    }
}

// ---------------- SPMM: t16[row,:] = sum val*h16[col,:] + A2[row]*x016[row,:]
__global__ void spmm_kernel(const __half* __restrict__ h,
                            const float* __restrict__ A2) {
    int row  = blockIdx.x * 8 + (threadIdx.x >> 5);
    int lane = threadIdx.x & 31;
    if (row >= NN) return;
    int s = g_rowstart[row];
    int e = g_rowstart[row + 1];
    float acc[8];
    #pragma unroll
    for (int q = 0; q < 8; q++) acc[q] = 0.f;

    #pragma unroll 4
    for (int p = s; p < e; ++p) {
        int2 ev = __ldg(&g_epack[p]);
        float v = __int_as_float(ev.y);
        uint4 raw = __ldg(((const uint4*)(h + (size_t)ev.x * FH)) + lane);
        const __half2* hh = (const __half2*)&raw;
        #pragma unroll
        for (int q = 0; q < 4; q++) {
            float2 f = __half22float2(hh[q]);
            acc[2 * q]     += v * f.x;
            acc[2 * q + 1] += v * f.y;
        }
    }
    float a = __ldg(&A2[row]);
    uint4 xraw = __ldg(((const uint4*)(g_x016 + (size_t)row * FH)) + lane);
    const __half2* xh = (const __half2*)&xraw;
    #pragma unroll
    for (int q = 0; q < 4; q++) {
        float2 f = __half22float2(xh[q]);
        acc[2 * q]     += a * f.x;
        acc[2 * q + 1] += a * f.y;
    }
    uint4 o;
    #pragma unroll
    for (int q = 0; q < 4; q++)
        ((__half2*)&o)[q] = __floats2half2_rn(acc[2 * q], acc[2 * q + 1]);
    ((uint4*)(g_t16 + (size_t)row * FH))[lane] = o;
}

// ---------------- fp16 tensor-core GEMM, cp.async double-buffered ------------
// MODE 0: relu(acc+bias) -> fp16 O1 AND O2
// MODE 1: relu(acc+bias) -> fp16 O1
// MODE 2: acc+bias       -> fp32 OF
__device__ __forceinline__ void mma_f16(float* d, const uint32_t* a, const uint32_t* b) {
    asm volatile(
        "mma.sync.aligned.m16n8k16.row.col.f32.f16.f16.f32 "
        "{%0,%1,%2,%3}, {%4,%5,%6,%7}, {%8,%9}, {%0,%1,%2,%3};\n"
        : "+f"(d[0]), "+f"(d[1]), "+f"(d[2]), "+f"(d[3])
        : "r"(a[0]), "r"(a[1]), "r"(a[2]), "r"(a[3]),
          "r"(b[0]), "r"(b[1]));
}

__device__ __forceinline__ void cp16(uint32_t smem_addr, const void* gptr, bool pred) {
    int sz = pred ? 16 : 0;
    asm volatile("cp.async.cg.shared.global [%0], [%1], 16, %2;\n"
                 :: "r"(smem_addr), "l"(gptr), "r"(sz));
}

template <int MODE>
__global__ __launch_bounds__(256, 2)
void gemm_f16_kernel(const __half* __restrict__ A, const __half* __restrict__ Bt,
                     const float* __restrict__ bias, float* __restrict__ OF,
                     __half* __restrict__ O1, __half* __restrict__ O2,
                     int M, int K, int Nc) {
    __shared__ __half As[2][128][40];
    __shared__ __half Bs[2][128][40];

    const int tid = threadIdx.x;
    const int wid = tid >> 5;
    const int lane = tid & 31;
    const int gid = lane >> 2;
    const int tig = lane & 3;
    const int wm = wid & 3;
    const int wn = wid >> 2;
    const int m0 = blockIdx.y * 128;
    const int n0 = blockIdx.x * 128;
    const int NT = K >> 5;

    // per-thread load coords (2 chunks each for A and B per tile)
    const int lr0 = tid >> 2;              // 0..63
    const int lr1 = lr0 + 64;              // 64..127
    const int lg  = (tid & 3) * 8;         // half offset within 32-k tile

    float acc[2][8][4];
    #pragma unroll
    for (int i = 0; i < 2; i++)
        #pragma unroll
        for (int j = 0; j < 8; j++)
            #pragma unroll
            for (int q = 0; q < 4; q++) acc[i][j][q] = 0.f;

    auto issue_tile = [&](int t, int buf) {
        int k0 = t * 32;
        // A rows
        {
            int gm0 = m0 + lr0, gm1 = m0 + lr1;
            bool p0 = gm0 < M, p1 = gm1 < M;
            const __half* s0 = A + (size_t)(p0 ? gm0 : 0) * K + k0 + lg;
            const __half* s1 = A + (size_t)(p1 ? gm1 : 0) * K + k0 + lg;
            cp16((uint32_t)__cvta_generic_to_shared(&As[buf][lr0][lg]), s0, p0);
            cp16((uint32_t)__cvta_generic_to_shared(&As[buf][lr1][lg]), s1, p1);
        }
        // B rows (Bt is [Nc][K])
        {
            int gn0 = n0 + lr0, gn1 = n0 + lr1;
            bool p0 = gn0 < Nc, p1 = gn1 < Nc;
            const __half* s0 = Bt + (size_t)(p0 ? gn0 : 0) * K + k0 + lg;
            const __half* s1 = Bt + (size_t)(p1 ? gn1 : 0) * K + k0 + lg;
            cp16((uint32_t)__cvta_generic_to_shared(&Bs[buf][lr0][lg]), s0, p0);
            cp16((uint32_t)__cvta_generic_to_shared(&Bs[buf][lr1][lg]), s1, p1);
        }
        asm volatile("cp.async.commit_group;\n");
    };

    issue_tile(0, 0);

    for (int t = 0; t < NT; t++) {
        int buf = t & 1;
        if (t + 1 < NT) {
            issue_tile(t + 1, (t + 1) & 1);
            asm volatile("cp.async.wait_group 1;\n");
        } else {
            asm volatile("cp.async.wait_group 0;\n");
        }
        __syncthreads();

        #pragma unroll
        for (int kk = 0; kk < 32; kk += 16) {
            uint32_t afr[2][4];
            #pragma unroll
            for (int mt = 0; mt < 2; mt++) {
                int r = wm * 32 + mt * 16 + gid;
                afr[mt][0] = *(const uint32_t*)&As[buf][r    ][kk + tig * 2];
                afr[mt][1] = *(const uint32_t*)&As[buf][r + 8][kk + tig * 2];
                afr[mt][2] = *(const uint32_t*)&As[buf][r    ][kk + tig * 2 + 8];
                afr[mt][3] = *(const uint32_t*)&As[buf][r + 8][kk + tig * 2 + 8];
            }
            uint32_t bfr[8][2];
            #pragma unroll
            for (int nt = 0; nt < 8; nt++) {
                int cc = wn * 64 + nt * 8 + gid;
                bfr[nt][0] = *(const uint32_t*)&Bs[buf][cc][kk + tig * 2];
                bfr[nt][1] = *(const uint32_t*)&Bs[buf][cc][kk + tig * 2 + 8];
            }
            #pragma unroll
            for (int mt = 0; mt < 2; mt++)
                #pragma unroll
                for (int nt = 0; nt < 8; nt++)
                    mma_f16(acc[mt][nt], afr[mt], bfr[nt]);
        }
        __syncthreads();
    }

    // epilogue
    #pragma unroll
    for (int mt = 0; mt < 2; mt++) {
        #pragma unroll
        for (int hm = 0; hm < 2; hm++) {
            int r = m0 + wm * 32 + mt * 16 + hm * 8 + gid;
            if (r >= M) continue;
            #pragma unroll
            for (int nt = 0; nt < 8; nt++) {
                int c = n0 + wn * 64 + nt * 8 + tig * 2;
                if (c >= Nc) continue;
                float v0 = acc[mt][nt][hm * 2]     + __ldg(&bias[c]);
                float v1 = acc[mt][nt][hm * 2 + 1] + __ldg(&bias[c + 1]);
                if (MODE != 2) {
                    v0 = fmaxf(v0, 0.f); v1 = fmaxf(v1, 0.f);
                    __half2 hv = __floats2half2_rn(v0, v1);
                    *(__half2*)(O1 + (size_t)r * Nc + c) = hv;
                    if (MODE == 0)
                        *(__half2*)(O2 + (size_t)r * Nc + c) = hv;
                } else {
                    float* op = OF + (size_t)r * Nc + c;
                    op[0] = v0; op[1] = v1;
                }
            }
        }
    }
}

// ---------------- launch ------------------------------------------------------
extern "C" void kernel_launch(void* const* d_in, const int* in_sizes, int n_in,
                              void* d_out, int out_size) {
    const float* x    = (const float*)d_in[0];
    const int*   erow = (const int*)  d_in[1];
    const int*   ecol = (const int*)  d_in[2];
    const float* eval = (const float*)d_in[3];
    const float* A2   = (const float*)d_in[4];
    const float* W1   = (const float*)d_in[5];
    const float* b1   = (const float*)d_in[6];
    const float* W3   = (const float*)d_in[7];
    const float* b3   = (const float*)d_in[8];
    const float* W2   = (const float*)d_in[9];
    const float* b2   = (const float*)d_in[10];
    float* out = (float*)d_out;

    __half *px16, *px016, *ph16, *pt16, *pW1t, *pW3p, *pW2t;
    cudaGetSymbolAddress((void**)&px16,  g_x16);
    cudaGetSymbolAddress((void**)&px016, g_x016);
    cudaGetSymbolAddress((void**)&ph16,  g_h16);
    cudaGetSymbolAddress((void**)&pt16,  g_t16);
    cudaGetSymbolAddress((void**)&pW1t,  g_W1t);
    cudaGetSymbolAddress((void**)&pW3p,  g_W3p);
    cudaGetSymbolAddress((void**)&pW2t,  g_W2t);

    // ---- conversions ----
    x2h_kernel<<<(int)(((size_t)NN * FIN / 8 + 255) / 256), 256>>>(x);
    wt_kernel<<<(FIN * FH + 255) / 256, 256>>>(W1, pW1t, FIN, FH, 0);
    wt_kernel<<<(FH * FH + 255) / 256, 256>>>(W3, pW3p, FH, FH, 1);
    wt_kernel<<<(FH * FOUT + 255) / 256, 256>>>(W2, pW2t, FH, FOUT, 0);

    // ---- CSR build ----
    zero_cnt_kernel<<<(NN + 255) / 256, 256>>>();
    hist_kernel<<<(EE + 255) / 256, 256>>>(erow);
    scan_kernel<<<1, 1024>>>();
    scatter_kernel<<<(EE + 255) / 256, 256>>>(erow, ecol, eval);

    // ---- x0 = relu(x @ W1 + b1) -> h16 and x016 ----
    dim3 grid1((FH + 127) / 128, (NN + 127) / 128);
    gemm_f16_kernel<0><<<grid1, 256>>>(px16, pW1t, b1, nullptr, ph16, px016,
                                       NN, FIN, FH);

    // ---- 10 hops ----
    dim3 grid3((FH + 127) / 128, (NN + 127) / 128);
    for (int i = 0; i < HOPS; i++) {
        spmm_kernel<<<(NN + 7) / 8, 256>>>(ph16, A2);
        gemm_f16_kernel<1><<<grid3, 256>>>(pt16, pW3p, b3, nullptr, ph16,
                                           nullptr, NN, FH, FH);
    }

    // ---- out = h16 @ W2 + b2 ----
    dim3 grid2((FOUT + 127) / 128, (NN + 127) / 128);
    gemm_f16_kernel<2><<<grid2, 256>>>(ph16, pW2t, b2, out, nullptr,
                                       nullptr, NN, FH, FOUT);
}

// round 7
// speedup vs baseline: 1.0456x; 1.0456x over previous
#include <cuda_runtime.h>
#include <cuda_fp16.h>
#include <cstdint>

#define NN   100000
#define EE   3200000
#define FH   256
#define FIN  512
#define FOUT 64
#define HOPS 10

// ---------------- scratch (device globals) ----------------------------------
__device__ __half g_x16 [(size_t)NN * FIN];
__device__ __half g_x016[(size_t)NN * FH];
__device__ __half g_h16 [(size_t)NN * FH];
__device__ __half g_t16 [(size_t)NN * FH];
__device__ __half g_W1t [(size_t)FIN * FH];
__device__ __half g_W3p [(size_t)FH * FH];   // (W3 + I)^T, [n][k]
__device__ __half g_W2t [(size_t)FH * FOUT];
__device__ int    g_rowstart[NN + 1];
__device__ int    g_cnt[NN];
__device__ int2   g_epack[EE];

// ---------------- conversions ------------------------------------------------
__global__ void x2h_kernel(const float* __restrict__ x) {
    size_t i = (size_t)blockIdx.x * blockDim.x + threadIdx.x;
    if (i >= (size_t)NN * FIN / 8) return;
    float4 a = __ldg(((const float4*)x) + 2 * i);
    float4 b = __ldg(((const float4*)x) + 2 * i + 1);
    uint4 o;
    ((__half2*)&o)[0] = __floats2half2_rn(a.x, a.y);
    ((__half2*)&o)[1] = __floats2half2_rn(a.z, a.w);
    ((__half2*)&o)[2] = __floats2half2_rn(b.x, b.y);
    ((__half2*)&o)[3] = __floats2half2_rn(b.z, b.w);
    ((uint4*)g_x16)[i] = o;
}

__global__ void wt_kernel(const float* __restrict__ W, __half* __restrict__ Bt,
                          int K, int Nc, int addI) {
    int i = blockIdx.x * blockDim.x + threadIdx.x;
    if (i >= K * Nc) return;
    int n = i / K, k = i % K;
    float v = __ldg(&W[(size_t)k * Nc + n]);
    if (addI && k == n) v += 1.0f;
    Bt[i] = __float2half_rn(v);
}

// ---------------- CSR build --------------------------------------------------
__global__ void zero_cnt_kernel() {
    int i = blockIdx.x * blockDim.x + threadIdx.x;
    if (i < NN) g_cnt[i] = 0;
}

__global__ void hist_kernel(const int* __restrict__ erow) {
    int e = blockIdx.x * blockDim.x + threadIdx.x;
    if (e < EE) atomicAdd(&g_cnt[erow[e]], 1);
}

// exclusive scan; seeds g_cnt with offsets (scatter cursor)
__global__ void scan_kernel() {
    __shared__ int wsum[32];
    __shared__ int carry_s;
    int t = threadIdx.x, lane = t & 31, w = t >> 5;
    if (t == 0) carry_s = 0;
    __syncthreads();
    for (int base = 0; base < NN; base += 1024) {
        int i = base + t;
        int v = (i < NN) ? g_cnt[i] : 0;
        int s = v;
        #pragma unroll
        for (int off = 1; off < 32; off <<= 1) {
            int u = __shfl_up_sync(0xffffffff, s, off);
            if (lane >= off) s += u;
        }
        if (lane == 31) wsum[w] = s;
        __syncthreads();
        if (w == 0) {
            int ws = wsum[lane];
            #pragma unroll
            for (int off = 1; off < 32; off <<= 1) {
                int u = __shfl_up_sync(0xffffffff, ws, off);
                if (lane >= off) ws += u;
            }
            wsum[lane] = ws;
        }
        __syncthreads();
        int wpre = (w == 0) ? 0 : wsum[w - 1];
        if (i < NN) {
            int rs = carry_s + wpre + s - v;
            g_rowstart[i] = rs;
            g_cnt[i] = rs;          // scatter cursor
        }
        __syncthreads();
        if (t == 1023) carry_s += wsum[31];
        __syncthreads();
    }
    if (threadIdx.x == 0) g_rowstart[NN] = carry_s;
}

__global__ void scatter_kernel(const int* __restrict__ erow,
                               const int* __restrict__ ecol,
                               const float* __restrict__ eval) {
    int e = blockIdx.x * blockDim.x + threadIdx.x;
    if (e < EE) {
        int p = atomicAdd(&g_cnt[erow[e]], 1);
        g_epack[p] = make_int2(ecol[e], __float_as_int(eval[e]));
    }
}

// ---------------- SPMM (R4 version) -------------------------------------------
__global__ void spmm_kernel(const __half* __restrict__ h,
                            const float* __restrict__ A2) {
    int row  = blockIdx.x * 8 + (threadIdx.x >> 5);
    int lane = threadIdx.x & 31;
    if (row >= NN) return;
    int s = g_rowstart[row];
    int e = g_rowstart[row + 1];
    float acc[8];
    #pragma unroll
    for (int q = 0; q < 8; q++) acc[q] = 0.f;

    #pragma unroll 2
    for (int p = s; p < e; ++p) {
        int2 ev = __ldg(&g_epack[p]);
        float v = __int_as_float(ev.y);
        uint4 raw = __ldg(((const uint4*)(h + (size_t)ev.x * FH)) + lane);
        const __half2* hh = (const __half2*)&raw;
        #pragma unroll
        for (int q = 0; q < 4; q++) {
            float2 f = __half22float2(hh[q]);
            acc[2 * q]     += v * f.x;
            acc[2 * q + 1] += v * f.y;
        }
    }
    float a = __ldg(&A2[row]);
    uint4 xraw = __ldg(((const uint4*)(g_x016 + (size_t)row * FH)) + lane);
    const __half2* xh = (const __half2*)&xraw;
    #pragma unroll
    for (int q = 0; q < 4; q++) {
        float2 f = __half22float2(xh[q]);
        acc[2 * q]     += a * f.x;
        acc[2 * q + 1] += a * f.y;
    }
    uint4 o;
    #pragma unroll
    for (int q = 0; q < 4; q++)
        ((__half2*)&o)[q] = __floats2half2_rn(acc[2 * q], acc[2 * q + 1]);
    ((uint4*)(g_t16 + (size_t)row * FH))[lane] = o;
}

// ---------------- fp16 mma.sync GEMM with ldmatrix frag loads -----------------
// MODE 0: relu(acc+bias) -> fp16 O1 AND O2
// MODE 1: relu(acc+bias) -> fp16 O1
// MODE 2: acc+bias       -> fp32 OF
__device__ __forceinline__ void mma_f16(float* d, const uint32_t* a, const uint32_t* b) {
    asm volatile(
        "mma.sync.aligned.m16n8k16.row.col.f32.f16.f16.f32 "
        "{%0,%1,%2,%3}, {%4,%5,%6,%7}, {%8,%9}, {%0,%1,%2,%3};\n"
        : "+f"(d[0]), "+f"(d[1]), "+f"(d[2]), "+f"(d[3])
        : "r"(a[0]), "r"(a[1]), "r"(a[2]), "r"(a[3]),
          "r"(b[0]), "r"(b[1]));
}

__device__ __forceinline__ void ldsm_x4(uint32_t& r0, uint32_t& r1,
                                        uint32_t& r2, uint32_t& r3,
                                        const void* p) {
    uint32_t a = (uint32_t)__cvta_generic_to_shared(p);
    asm volatile("ldmatrix.sync.aligned.m8n8.x4.shared.b16 {%0,%1,%2,%3}, [%4];"
                 : "=r"(r0), "=r"(r1), "=r"(r2), "=r"(r3) : "r"(a));
}

template <int MODE>
__global__ __launch_bounds__(256, 2)
void gemm_f16_kernel(const __half* __restrict__ A, const __half* __restrict__ Bt,
                     const float* __restrict__ bias, float* __restrict__ OF,
                     __half* __restrict__ O1, __half* __restrict__ O2,
                     int M, int K, int Nc) {
    __shared__ __half As[128][40];
    __shared__ __half Bs[128][40];

    const int tid = threadIdx.x;
    const int wid = tid >> 5;
    const int lane = tid & 31;
    const int gid = lane >> 2;
    const int tig = lane & 3;
    const int wm = wid & 3;      // rows wm*32
    const int wn = wid >> 2;     // cols wn*64
    const int m0 = blockIdx.y * 128;
    const int n0 = blockIdx.x * 128;

    // ldmatrix lane-address components
    const int a_row_off = (lane & 7) + ((lane >> 3) & 1) * 8;   // row within 16
    const int a_k_off   = (lane >> 4) * 8;                      // 0 or 8

    float acc[2][8][4];
    #pragma unroll
    for (int i = 0; i < 2; i++)
        #pragma unroll
        for (int j = 0; j < 8; j++)
            #pragma unroll
            for (int q = 0; q < 4; q++) acc[i][j][q] = 0.f;

    for (int k0 = 0; k0 < K; k0 += 32) {
        #pragma unroll
        for (int i = 0; i < 2; i++) {
            int id = tid + i * 256;
            int r  = id >> 2;
            int g  = id & 3;
            int gm = m0 + r;
            uint4 av = make_uint4(0u, 0u, 0u, 0u);
            if (gm < M)
                av = *(const uint4*)(A + (size_t)gm * K + k0 + g * 8);
            *(uint4*)&As[r][g * 8] = av;
        }
        #pragma unroll
        for (int i = 0; i < 2; i++) {
            int id = tid + i * 256;
            int r  = id >> 2;
            int g  = id & 3;
            int gn = n0 + r;
            uint4 bv = make_uint4(0u, 0u, 0u, 0u);
            if (gn < Nc)
                bv = *(const uint4*)(Bt + (size_t)gn * K + k0 + g * 8);
            *(uint4*)&Bs[r][g * 8] = bv;
        }
        __syncthreads();

        #pragma unroll
        for (int kk = 0; kk < 32; kk += 16) {
            uint32_t afr[2][4];
            #pragma unroll
            for (int mt = 0; mt < 2; mt++) {
                // mat0: rows R..R+7 @kk, mat1: R+8..R+15 @kk, mat2/3: same @kk+8
                const __half* p = &As[wm * 32 + mt * 16 + a_row_off][kk + a_k_off];
                ldsm_x4(afr[mt][0], afr[mt][1], afr[mt][2], afr[mt][3], p);
            }
            uint32_t bfr[8][2];
            {
                // lane l -> row n0w + l ; 4 mats = nt 0..3
                const __half* p0 = &Bs[wn * 64 + lane][kk];
                const __half* p1 = &Bs[wn * 64 + 32 + lane][kk];
                const __half* p2 = &Bs[wn * 64 + lane][kk + 8];
                const __half* p3 = &Bs[wn * 64 + 32 + lane][kk + 8];
                ldsm_x4(bfr[0][0], bfr[1][0], bfr[2][0], bfr[3][0], p0);
                ldsm_x4(bfr[4][0], bfr[5][0], bfr[6][0], bfr[7][0], p1);
                ldsm_x4(bfr[0][1], bfr[1][1], bfr[2][1], bfr[3][1], p2);
                ldsm_x4(bfr[4][1], bfr[5][1], bfr[6][1], bfr[7][1], p3);
            }
            #pragma unroll
            for (int mt = 0; mt < 2; mt++)
                #pragma unroll
                for (int nt = 0; nt < 8; nt++)
                    mma_f16(acc[mt][nt], afr[mt], bfr[nt]);
        }
        __syncthreads();
    }

    #pragma unroll
    for (int mt = 0; mt < 2; mt++) {
        #pragma unroll
        for (int hm = 0; hm < 2; hm++) {
            int r = m0 + wm * 32 + mt * 16 + hm * 8 + gid;
            if (r >= M) continue;
            #pragma unroll
            for (int nt = 0; nt < 8; nt++) {
                int c = n0 + wn * 64 + nt * 8 + tig * 2;
                if (c >= Nc) continue;
                float v0 = acc[mt][nt][hm * 2]     + __ldg(&bias[c]);
                float v1 = acc[mt][nt][hm * 2 + 1] + __ldg(&bias[c + 1]);
                if (MODE != 2) {
                    v0 = fmaxf(v0, 0.f); v1 = fmaxf(v1, 0.f);
                    __half2 hv = __floats2half2_rn(v0, v1);
                    *(__half2*)(O1 + (size_t)r * Nc + c) = hv;
                    if (MODE == 0)
                        *(__half2*)(O2 + (size_t)r * Nc + c) = hv;
                } else {
                    float* op = OF + (size_t)r * Nc + c;
                    op[0] = v0; op[1] = v1;
                }
            }
        }
    }
}

// ---------------- launch ------------------------------------------------------
extern "C" void kernel_launch(void* const* d_in, const int* in_sizes, int n_in,
                              void* d_out, int out_size) {
    const float* x    = (const float*)d_in[0];
    const int*   erow = (const int*)  d_in[1];
    const int*   ecol = (const int*)  d_in[2];
    const float* eval = (const float*)d_in[3];
    const float* A2   = (const float*)d_in[4];
    const float* W1   = (const float*)d_in[5];
    const float* b1   = (const float*)d_in[6];
    const float* W3   = (const float*)d_in[7];
    const float* b3   = (const float*)d_in[8];
    const float* W2   = (const float*)d_in[9];
    const float* b2   = (const float*)d_in[10];
    float* out = (float*)d_out;

    __half *px16, *px016, *ph16, *pt16, *pW1t, *pW3p, *pW2t;
    cudaGetSymbolAddress((void**)&px16,  g_x16);
    cudaGetSymbolAddress((void**)&px016, g_x016);
    cudaGetSymbolAddress((void**)&ph16,  g_h16);
    cudaGetSymbolAddress((void**)&pt16,  g_t16);
    cudaGetSymbolAddress((void**)&pW1t,  g_W1t);
    cudaGetSymbolAddress((void**)&pW3p,  g_W3p);
    cudaGetSymbolAddress((void**)&pW2t,  g_W2t);

    // ---- conversions ----
    x2h_kernel<<<(int)(((size_t)NN * FIN / 8 + 255) / 256), 256>>>(x);
    wt_kernel<<<(FIN * FH + 255) / 256, 256>>>(W1, pW1t, FIN, FH, 0);
    wt_kernel<<<(FH * FH + 255) / 256, 256>>>(W3, pW3p, FH, FH, 1);
    wt_kernel<<<(FH * FOUT + 255) / 256, 256>>>(W2, pW2t, FH, FOUT, 0);

    // ---- CSR build ----
    zero_cnt_kernel<<<(NN + 255) / 256, 256>>>();
    hist_kernel<<<(EE + 255) / 256, 256>>>(erow);
    scan_kernel<<<1, 1024>>>();
    scatter_kernel<<<(EE + 255) / 256, 256>>>(erow, ecol, eval);

    // ---- x0 = relu(x @ W1 + b1) -> h16 and x016 ----
    dim3 grid1((FH + 127) / 128, (NN + 127) / 128);
    gemm_f16_kernel<0><<<grid1, 256>>>(px16, pW1t, b1, nullptr, ph16, px016,
                                       NN, FIN, FH);

    // ---- 10 hops ----
    dim3 grid3((FH + 127) / 128, (NN + 127) / 128);
    for (int i = 0; i < HOPS; i++) {
        spmm_kernel<<<(NN + 7) / 8, 256>>>(ph16, A2);
        gemm_f16_kernel<1><<<grid3, 256>>>(pt16, pW3p, b3, nullptr, ph16,
                                           nullptr, NN, FH, FH);
    }

    // ---- out = h16 @ W2 + b2 ----
    dim3 grid2((FOUT + 127) / 128, (NN + 127) / 128);
    gemm_f16_kernel<2><<<grid2, 256>>>(ph16, pW2t, b2, out, nullptr,
                                       nullptr, NN, FH, FOUT);
}